// round 3
// baseline (speedup 1.0000x reference)
#include <cuda_runtime.h>

// UndistortLayer: B=16, C=3, H=W=512, fp32.
// Tiled version: each block handles a 32x32 output tile of one image.
// k<0 guarantees the distortion map is a contraction (source span <= tile span),
// so the source bounding box of a 32x32 tile fits in 48x48 with margins.
// Source bbox is staged in shared memory (3 planes); bilinear gather runs on smem.

#define UD_W 512
#define UD_H 512
#define UD_HW (UD_W * UD_H)       // 2^18
#define TW 32
#define TH 32
#define SD 48                      // smem tile rows/cols (max bbox dim)
#define SP 49                      // row pitch (odd -> bank spread)

__global__ __launch_bounds__(256) void undistort_tile_kernel(
    const float* __restrict__ im,   // [B, 3, H, W]
    const float* __restrict__ kArr, // [B]
    const float* __restrict__ dxArr,// [B]
    const float* __restrict__ dyArr,// [B]
    float* __restrict__ out)        // [B, 3, H, W]
{
    __shared__ float tile[3][SD * SP];   // 3 * 48 * 49 * 4 = 28224 B

    const int txi = blockIdx.x;          // tile col index (0..15)
    const int tyi = blockIdx.y;          // tile row index (0..15)
    const int b   = blockIdx.z;          // batch (0..15)
    const int gx0 = txi * TW;
    const int gy0 = tyi * TH;
    const int tid = threadIdx.x;
    const int lane = tid & 31;
    const int wrp  = tid >> 5;           // 0..7

    const float k  = __ldg(&kArr[b]);
    const float dx = __ldg(&dxArr[b]);
    const float dy = __ldg(&dyArr[b]);
    const float invW = 1.0f / (float)UD_W;
    const float invH = 1.0f / (float)UD_H;

    // ---- Conservative source bbox (computed redundantly by every thread) ----
    // Map is monotone in each coord; xd extremes over a rectangle occur at
    // xur endpoints combined with |yur| min/max (|yur| min point = clamp of the
    // yur=0 line into the tile). 3x3 candidate grid covers all extremes.
    const float xmidc = fminf(fmaxf(dx + 0.5f * UD_W, (float)gx0), (float)(gx0 + TW - 1));
    const float ymidc = fminf(fmaxf(dy + 0.5f * UD_H, (float)gy0), (float)(gy0 + TH - 1));
    const float xs[3] = { (float)gx0, (float)(gx0 + TW - 1), xmidc };
    const float ys[3] = { (float)gy0, (float)(gy0 + TH - 1), ymidc };

    float xdmin = 1e30f, xdmax = -1e30f, ydmin = 1e30f, ydmax = -1e30f;
    #pragma unroll
    for (int iy = 0; iy < 3; ++iy) {
        const float yur = (ys[iy] - dy) * invH - 0.5f;
        #pragma unroll
        for (int ix = 0; ix < 3; ++ix) {
            const float xur = (xs[ix] - dx) * invW - 0.5f;
            const float ru2 = xur * xur + yur * yur;
            const float inv = 1.0f / (1.0f - k * ru2);
            const float xd = (xur * inv + 0.5f) * (float)UD_W + dx;
            const float yd = (yur * inv + 0.5f) * (float)UD_H + dy;
            xdmin = fminf(xdmin, xd); xdmax = fmaxf(xdmax, xd);
            ydmin = fminf(ydmin, yd); ydmax = fmaxf(ydmax, yd);
        }
    }
    const int bx0 = max(0, (int)floorf(xdmin) - 2);
    const int bx1 = min(UD_W - 1, (int)ceilf(xdmax) + 2);
    const int by0 = max(0, (int)floorf(ydmin) - 2);
    const int by1 = min(UD_H - 1, (int)ceilf(ydmax) + 2);
    int bw = bx1 - bx0 + 1; if (bw > SD) bw = SD;
    int bh = by1 - by0 + 1; if (bh > SD) bh = SD;

    // ---- Cooperative load of source bbox into smem (coalesced) ----
    const float* imb = im + (size_t)b * 3 * UD_HW;
    #pragma unroll
    for (int c = 0; c < 3; ++c) {
        const float* plane = imb + c * UD_HW;
        for (int r = wrp; r < bh; r += 8) {
            const float* src = plane + (by0 + r) * UD_W + bx0;
            float* dst = &tile[c][r * SP];
            for (int col = lane; col < bw; col += 32)
                dst[col] = __ldg(src + col);
        }
    }
    __syncthreads();

    // ---- Per-pixel gather from smem ----
    const int x = gx0 + lane;                      // lanes -> consecutive x
    const float xur = ((float)x - dx) * invW - 0.5f;
    const float xur2 = xur * xur;
    float* outb = out + (size_t)b * 3 * UD_HW + (size_t)x;

    #pragma unroll
    for (int p = 0; p < 4; ++p) {
        const int y = gy0 + wrp + 8 * p;
        const float yur = ((float)y - dy) * invH - 0.5f;
        const float ru2 = xur2 + yur * yur;
        const float inv = 1.0f / (1.0f - k * ru2);

        const float xd = (xur * inv + 0.5f) * (float)UD_W + dx;
        const float yd = (yur * inv + 0.5f) * (float)UD_H + dy;

        const float fx = floorf(xd);
        const float fy = floorf(yd);
        const float ox = xd - fx;
        const float oy = yd - fy;

        int xfi = min(max((int)fx, 0), UD_W - 1);
        int xci = min(max((int)ceilf(xd), 0), UD_W - 1);
        int yfi = min(max((int)fy, 0), UD_H - 1);
        int yci = min(max((int)ceilf(yd), 0), UD_H - 1);

        // local (bbox-relative) indices; clamp is safety net only
        const int lxf = min(max(xfi - bx0, 0), bw - 1);
        const int lxc = min(max(xci - bx0, 0), bw - 1);
        const int lyf = min(max(yfi - by0, 0), bh - 1);
        const int lyc = min(max(yci - by0, 0), bh - 1);

        const int i00 = lyf * SP + lxf;
        const int i01 = lyf * SP + lxc;
        const int i10 = lyc * SP + lxf;
        const int i11 = lyc * SP + lxc;

        const float w00 = (1.0f - ox) * (1.0f - oy);
        const float w01 = ox * (1.0f - oy);
        const float w10 = (1.0f - ox) * oy;
        const float w11 = ox * oy;

        float* orow = outb + (size_t)y * UD_W;
        #pragma unroll
        for (int c = 0; c < 3; ++c) {
            const float v00 = tile[c][i00];
            const float v01 = tile[c][i01];
            const float v10 = tile[c][i10];
            const float v11 = tile[c][i11];
            orow[(size_t)c * UD_HW] =
                w00 * v00 + w01 * v01 + w10 * v10 + w11 * v11;
        }
    }
}

extern "C" void kernel_launch(void* const* d_in, const int* in_sizes, int n_in,
                              void* d_out, int out_size) {
    const float* im = (const float*)d_in[0];
    const float* k  = (const float*)d_in[1];
    const float* dx = (const float*)d_in[2];
    const float* dy = (const float*)d_in[3];
    float* out = (float*)d_out;

    dim3 grid(UD_W / TW, UD_H / TH, 16);   // 16 x 16 x 16 = 4096 blocks
    undistort_tile_kernel<<<grid, 256>>>(im, k, dx, dy, out);
}

// round 4
// speedup vs baseline: 2.1429x; 2.1429x over previous
#include <cuda_runtime.h>

// UndistortLayer: B=16, C=3, H=W=512, fp32.
// 1 pixel per thread, lanes consecutive in x -> each gather LDG warp-wide
// spans only ~32 consecutive source pixels (~2 cache lines) instead of ~128
// (Round-1 layout). 12 gathers/pixel, channel plane offsets fold into LDG
// immediate offsets.

#define UD_W 512
#define UD_H 512
#define UD_HW (UD_W * UD_H)          // 2^18
#define UD_CHW (3 * UD_HW)

__global__ __launch_bounds__(256) void undistort_kernel(
    const float* __restrict__ im,   // [B, 3, H, W]
    const float* __restrict__ kArr, // [B]
    const float* __restrict__ dxArr,// [B]
    const float* __restrict__ dyArr,// [B]
    float* __restrict__ out)        // [B, 3, H, W]
{
    const int pix = blockIdx.x * 256 + threadIdx.x;  // lane-consecutive x
    const int b   = pix >> 18;                       // / HW
    const int rem = pix & (UD_HW - 1);
    const int y   = rem >> 9;                        // / W
    const int x   = rem & (UD_W - 1);

    const float k  = __ldg(&kArr[b]);
    const float dx = __ldg(&dxArr[b]);
    const float dy = __ldg(&dyArr[b]);

    const float invW = 1.0f / (float)UD_W;
    const float invH = 1.0f / (float)UD_H;

    const float xur = ((float)x - dx) * invW - 0.5f;
    const float yur = ((float)y - dy) * invH - 0.5f;
    const float ru2 = xur * xur + yur * yur;
    const float inv = 1.0f / (1.0f - k * ru2);

    const float xd = (xur * inv + 0.5f) * (float)UD_W + dx;
    const float yd = (yur * inv + 0.5f) * (float)UD_H + dy;

    const float fx = floorf(xd);
    const float fy = floorf(yd);
    const float ox = xd - fx;
    const float oy = yd - fy;

    int xfi = min(max((int)fx, 0), UD_W - 1);
    int xci = min(max((int)ceilf(xd), 0), UD_W - 1);
    int yfi = min(max((int)fy, 0), UD_H - 1);
    int yci = min(max((int)ceilf(yd), 0), UD_H - 1);

    const int i00 = yfi * UD_W + xfi;
    const int i01 = yfi * UD_W + xci;
    const int i10 = yci * UD_W + xfi;
    const int i11 = yci * UD_W + xci;

    const float w00 = (1.0f - ox) * (1.0f - oy);
    const float w01 = ox * (1.0f - oy);
    const float w10 = (1.0f - ox) * oy;
    const float w11 = ox * oy;

    const float* imb = im + (size_t)b * UD_CHW;
    float* outp = out + (size_t)b * UD_CHW + rem;

    // Channel 0
    {
        const float v00 = __ldg(imb + i00);
        const float v01 = __ldg(imb + i01);
        const float v10 = __ldg(imb + i10);
        const float v11 = __ldg(imb + i11);
        outp[0] = w00 * v00 + w01 * v01 + w10 * v10 + w11 * v11;
    }
    // Channel 1 (plane offset folds into LDG immediate)
    {
        const float v00 = __ldg(imb + UD_HW + i00);
        const float v01 = __ldg(imb + UD_HW + i01);
        const float v10 = __ldg(imb + UD_HW + i10);
        const float v11 = __ldg(imb + UD_HW + i11);
        outp[UD_HW] = w00 * v00 + w01 * v01 + w10 * v10 + w11 * v11;
    }
    // Channel 2
    {
        const float v00 = __ldg(imb + 2 * UD_HW + i00);
        const float v01 = __ldg(imb + 2 * UD_HW + i01);
        const float v10 = __ldg(imb + 2 * UD_HW + i10);
        const float v11 = __ldg(imb + 2 * UD_HW + i11);
        outp[2 * UD_HW] = w00 * v00 + w01 * v01 + w10 * v10 + w11 * v11;
    }
}

extern "C" void kernel_launch(void* const* d_in, const int* in_sizes, int n_in,
                              void* d_out, int out_size) {
    const float* im = (const float*)d_in[0];
    const float* k  = (const float*)d_in[1];
    const float* dx = (const float*)d_in[2];
    const float* dy = (const float*)d_in[3];
    float* out = (float*)d_out;

    const int total_pix = 16 * UD_HW;          // 4,194,304 threads
    const int block = 256;
    const int grid = total_pix / block;        // 16384
    undistort_kernel<<<grid, block>>>(im, k, dx, dy, out);
}

// round 6
// speedup vs baseline: 2.4935x; 1.1636x over previous
#include <cuda_runtime.h>

// UndistortLayer: B=16, C=3, H=W=512, fp32.
// 1 thread = 2 vertically adjacent pixels (same x). Lanes consecutive in x.
// Compact map: px=x-dx-256, py=y-dy-256, d=1-(k/512^2)(px^2+py^2),
// xd=px/d+256+dx, yd=py/d+256+dy. ceil replaced by clamp(floor+1)
// (identical result: corner weight is exactly 0 whenever they could differ).
// floor via __float2int_rd (single F2I.RD), frac via xd - (float)floor.

#define UD_W 512
#define UD_HW (512 * 512)            // 2^18
#define UD_CHW (3 * UD_HW)

__global__ __launch_bounds__(256) void undistort_kernel(
    const float* __restrict__ im,   // [B, 3, H, W]
    const float* __restrict__ kArr, // [B]
    const float* __restrict__ dxArr,// [B]
    const float* __restrict__ dyArr,// [B]
    float* __restrict__ out)        // [B, 3, H, W]
{
    const int t  = blockIdx.x * 256 + threadIdx.x;
    const int x  = t & 511;               // lane-consecutive x
    const int yp = (t >> 9) & 255;        // y-pair index
    const int b  = t >> 17;
    const int y0 = yp << 1;

    const float k  = __ldg(&kArr[b]);
    const float dx = __ldg(&dxArr[b]);
    const float dy = __ldg(&dyArr[b]);

    const float kw = k * (1.0f / (512.0f * 512.0f));
    const float cx = 256.0f + dx;
    const float cy = 256.0f + dy;
    const float px = (float)x - cx;       // x - dx - 256
    const float px2 = px * px;

    const float* imb = im + (size_t)b * UD_CHW;
    float* outb = out + (size_t)b * UD_CHW + (size_t)y0 * UD_W + x;

    #pragma unroll
    for (int iy = 0; iy < 2; ++iy) {
        const float py = (float)(y0 + iy) - cy;
        const float d  = fmaf(-kw, fmaf(py, py, px2), 1.0f);
        const float inv = __fdividef(1.0f, d);
        const float xd = fmaf(px, inv, cx);
        const float yd = fmaf(py, inv, cy);

        const int xfu = __float2int_rd(xd);   // floor as int, one instr
        const int yfu = __float2int_rd(yd);
        const float ox = xd - (float)xfu;
        const float oy = yd - (float)yfu;

        const int xfi = min(max(xfu, 0), 511);
        const int xci = min(max(xfu + 1, 0), 511);
        const int yfi = min(max(yfu, 0), 511);
        const int yci = min(max(yfu + 1, 0), 511);

        const int i00 = (yfi << 9) + xfi;
        const int i01 = (yfi << 9) + xci;
        const int i10 = (yci << 9) + xfi;
        const int i11 = (yci << 9) + xci;

        const float w00 = (1.0f - ox) * (1.0f - oy);
        const float w01 = ox * (1.0f - oy);
        const float w10 = (1.0f - ox) * oy;
        const float w11 = ox * oy;

        float* orow = outb + iy * UD_W;
        #pragma unroll
        for (int c = 0; c < 3; ++c) {
            const float* pl = imb + c * UD_HW;
            const float v00 = __ldg(pl + i00);
            const float v01 = __ldg(pl + i01);
            const float v10 = __ldg(pl + i10);
            const float v11 = __ldg(pl + i11);
            orow[c * UD_HW] = fmaf(w00, v00, fmaf(w01, v01, fmaf(w10, v10, w11 * v11)));
        }
    }
}

extern "C" void kernel_launch(void* const* d_in, const int* in_sizes, int n_in,
                              void* d_out, int out_size) {
    const float* im = (const float*)d_in[0];
    const float* k  = (const float*)d_in[1];
    const float* dx = (const float*)d_in[2];
    const float* dy = (const float*)d_in[3];
    float* out = (float*)d_out;

    const int total_threads = 16 * UD_HW / 2;   // 2,097,152
    const int block = 256;
    const int grid = total_threads / block;     // 8192
    undistort_kernel<<<grid, block>>>(im, k, dx, dy, out);
}